// round 1
// baseline (speedup 1.0000x reference)
#include <cuda_runtime.h>
#include <math.h>

#define H 256
#define NB_MAX 4096
#define MAXT (4096 * 99)
#define TM 64
#define KK 16
#define XS_STRIDE 264   // padded row stride for 64xH smem tiles

// ---- scratch (static __device__: allowed; no runtime allocation) ----
__device__ int   g_offs[NB_MAX + 1];
__device__ int   g_seg[MAXT];
__device__ float g_mean[NB_MAX * H];
__device__ float g_mg[NB_MAX * H];
__device__ float g_posproj[201 * H];
__device__ float g_alpha[MAXT];

// ---------------------------------------------------------------
// K1: exclusive prefix scan of seq_len -> g_offs  (1 block, 1024 thr)
// ---------------------------------------------------------------
__global__ void k_scan(const int* __restrict__ seq_len, int nb) {
    __shared__ int chunk[1024];
    int tid = threadIdx.x;
    int base = tid * 4;
    int v0 = (base + 0 < nb) ? seq_len[base + 0] : 0;
    int v1 = (base + 1 < nb) ? seq_len[base + 1] : 0;
    int v2 = (base + 2 < nb) ? seq_len[base + 2] : 0;
    int v3 = (base + 3 < nb) ? seq_len[base + 3] : 0;
    int p1 = v0, p2 = v0 + v1, p3 = p2 + v2, p4 = p3 + v3;
    chunk[tid] = p4;
    __syncthreads();
    for (int d = 1; d < 1024; d <<= 1) {
        int t = (tid >= d) ? chunk[tid - d] : 0;
        __syncthreads();
        chunk[tid] += t;
        __syncthreads();
    }
    int prev = (tid > 0) ? chunk[tid - 1] : 0;
    // each thread writes 5 entries; overlaps are identical values
    if (base + 0 <= nb) g_offs[base + 0] = prev;
    if (base + 1 <= nb) g_offs[base + 1] = prev + p1;
    if (base + 2 <= nb) g_offs[base + 2] = prev + p2;
    if (base + 3 <= nb) g_offs[base + 3] = prev + p3;
    if (base + 4 <= nb) g_offs[base + 4] = prev + p4;
}

// ---------------------------------------------------------------
// K2: per-session mean + segment-id fill. grid=nb, block=H(256)
// ---------------------------------------------------------------
__global__ void k_mean_seg(const float* __restrict__ hidden, int nb) {
    int b = blockIdx.x;
    if (b >= nb) return;
    int s = g_offs[b], e = g_offs[b + 1];
    int tid = threadIdx.x;
    float acc = 0.f;
    #pragma unroll 4
    for (int t = s; t < e; ++t) acc += hidden[t * H + tid];
    g_mean[b * H + tid] = acc / (float)(e - s);
    for (int t = s + tid; t < e; t += blockDim.x) g_seg[t] = b;
}

// ---------------------------------------------------------------
// K3: pos_proj[p,:] = pos_table[p,:] @ W_pos[H:,:] + b_pos. grid=201
// ---------------------------------------------------------------
__global__ void k_posproj(const float* __restrict__ pos_table,
                          const float* __restrict__ W_pos,
                          const float* __restrict__ b_pos) {
    __shared__ float row[H];
    int p = blockIdx.x;
    int c = threadIdx.x;
    row[c] = pos_table[p * H + c];
    __syncthreads();
    float acc = b_pos[c];
    #pragma unroll 8
    for (int k = 0; k < H; ++k)
        acc = fmaf(row[k], W_pos[(H + k) * H + c], acc);
    g_posproj[p * H + c] = acc;
}

// ---------------------------------------------------------------
// shared GEMM microkernel: [TM,H] (smem) @ [H,H] (gmem, slab-streamed)
// 256 threads as 16x16; each thread owns a 4x16 output microtile.
// Caller must preload slab 0 into Wsm[0] and __syncthreads().
// ---------------------------------------------------------------
__device__ __forceinline__ void gemm_tile(const float* __restrict__ Asm,
                                          const float* __restrict__ Wg,
                                          float* __restrict__ Wsm,
                                          float (&acc)[4][16],
                                          int tid, int r0, int c0) {
    const int NSLAB = H / KK;
    for (int s = 0; s < NSLAB; ++s) {
        const int cur = s & 1;
        if (s + 1 < NSLAB) {
            const float* src = Wg + (s + 1) * KK * H;
            float* dst = Wsm + (cur ^ 1) * (KK * H);
            #pragma unroll
            for (int i = 0; i < (KK * H / 4) / 256; ++i) {
                int idx = (tid + i * 256) * 4;
                *(float4*)&dst[idx] = *(const float4*)&src[idx];
            }
        }
        const float* Acol = Asm + r0 * XS_STRIDE + s * KK;
        const float* Wcur = Wsm + cur * (KK * H) + c0;
        #pragma unroll 4
        for (int kk = 0; kk < KK; ++kk) {
            float aa[4];
            #pragma unroll
            for (int j = 0; j < 4; ++j) aa[j] = Acol[j * XS_STRIDE + kk];
            float4 w0 = *(const float4*)&Wcur[kk * H + 0];
            float4 w1 = *(const float4*)&Wcur[kk * H + 4];
            float4 w2 = *(const float4*)&Wcur[kk * H + 8];
            float4 w3 = *(const float4*)&Wcur[kk * H + 12];
            float bb[16] = {w0.x, w0.y, w0.z, w0.w, w1.x, w1.y, w1.z, w1.w,
                            w2.x, w2.y, w2.z, w2.w, w3.x, w3.y, w3.z, w3.w};
            #pragma unroll
            for (int j = 0; j < 4; ++j)
                #pragma unroll
                for (int c = 0; c < 16; ++c)
                    acc[j][c] = fmaf(aa[j], bb[c], acc[j][c]);
        }
        __syncthreads();
    }
}

__device__ __forceinline__ void load_slab0(float* __restrict__ Wsm,
                                           const float* __restrict__ Wg, int tid) {
    #pragma unroll
    for (int i = 0; i < (KK * H / 4) / 256; ++i) {
        int idx = (tid + i * 256) * 4;
        *(float4*)&Wsm[idx] = *(const float4*)&Wg[idx];
    }
}

// ---------------------------------------------------------------
// K4: mg = mean @ W1 + b1   (grid = ceil(nb/TM))
// ---------------------------------------------------------------
extern __shared__ float smem_dyn[];

__global__ __launch_bounds__(256) void k_mg(const float* __restrict__ W1,
                                            const float* __restrict__ b1, int nb) {
    float* Xs = smem_dyn;                       // TM*XS_STRIDE
    float* Ws = Xs + TM * XS_STRIDE;            // 2*KK*H
    int tid = threadIdx.x;
    int rblk = blockIdx.x * TM;
    for (int i = tid; i < TM * (H / 4); i += 256) {
        int row = i >> 6, c4 = (i & 63) * 4;
        float4 v = make_float4(0.f, 0.f, 0.f, 0.f);
        if (rblk + row < nb) v = *(const float4*)&g_mean[(rblk + row) * H + c4];
        *(float4*)&Xs[row * XS_STRIDE + c4] = v;
    }
    load_slab0(Ws, W1, tid);
    __syncthreads();

    int ty = tid >> 4, tx = tid & 15, r0 = ty * 4, c0 = tx * 16;
    float acc[4][16];
    #pragma unroll
    for (int j = 0; j < 4; ++j)
        #pragma unroll
        for (int c = 0; c < 16; ++c) acc[j][c] = 0.f;

    gemm_tile(Xs, W1, Ws, acc, tid, r0, c0);

    float4 bv0 = *(const float4*)&b1[c0 + 0];
    float4 bv1 = *(const float4*)&b1[c0 + 4];
    float4 bv2 = *(const float4*)&b1[c0 + 8];
    float4 bv3 = *(const float4*)&b1[c0 + 12];
    float bb[16] = {bv0.x, bv0.y, bv0.z, bv0.w, bv1.x, bv1.y, bv1.z, bv1.w,
                    bv2.x, bv2.y, bv2.z, bv2.w, bv3.x, bv3.y, bv3.z, bv3.w};
    #pragma unroll
    for (int j = 0; j < 4; ++j) {
        int r = rblk + r0 + j;
        if (r < nb) {
            #pragma unroll
            for (int c = 0; c < 16; ++c)
                g_mg[r * H + c0 + c] = acc[j][c] + bb[c];
        }
    }
}

// ---------------------------------------------------------------
// K5: fused main per-token-tile kernel.
//   ph = tanh(X @ Wp_top + pos_proj[rp])
//   g  = sigmoid(ph @ W2 + b2 + mg[seg])
//   alpha = g . qw + qb
// ---------------------------------------------------------------
__global__ __launch_bounds__(256) void k_main(const float* __restrict__ hidden,
                                              const float* __restrict__ W_pos,
                                              const float* __restrict__ W2,
                                              const float* __restrict__ b2,
                                              const float* __restrict__ qw,
                                              const float* __restrict__ qb,
                                              const int* __restrict__ reverse_pos,
                                              int T) {
    float* Xs  = smem_dyn;                          // TM*XS_STRIDE
    float* PHs = Xs + TM * XS_STRIDE;               // TM*XS_STRIDE
    float* Ws  = PHs + TM * XS_STRIDE;              // 2*KK*H
    int*   rp_s  = (int*)(Ws + 2 * KK * H);         // TM
    int*   seg_s = rp_s + TM;                       // TM

    int tid = threadIdx.x;
    int t0 = blockIdx.x * TM;

    for (int i = tid; i < TM * (H / 4); i += 256) {
        int row = i >> 6, c4 = (i & 63) * 4;
        float4 v = make_float4(0.f, 0.f, 0.f, 0.f);
        if (t0 + row < T) v = *(const float4*)&hidden[(t0 + row) * H + c4];
        *(float4*)&Xs[row * XS_STRIDE + c4] = v;
    }
    if (tid < TM) {
        int t = t0 + tid;
        rp_s[tid]  = (t < T) ? reverse_pos[t] : 0;
        seg_s[tid] = (t < T) ? g_seg[t] : 0;
    }
    load_slab0(Ws, W_pos, tid);   // Wp_top = first H rows of W_pos
    __syncthreads();

    int ty = tid >> 4, tx = tid & 15, r0 = ty * 4, c0 = tx * 16;
    float acc[4][16];
    #pragma unroll
    for (int j = 0; j < 4; ++j)
        #pragma unroll
        for (int c = 0; c < 16; ++c) acc[j][c] = 0.f;

    // ---- GEMM A: X @ Wp_top ----
    gemm_tile(Xs, W_pos, Ws, acc, tid, r0, c0);

    // ---- epilogue A: + pos_proj gather, tanh, -> PHs ----
    #pragma unroll
    for (int j = 0; j < 4; ++j) {
        int m = r0 + j;
        const float* pp = &g_posproj[rp_s[m] * H + c0];
        float4 p0 = *(const float4*)&pp[0];
        float4 p1 = *(const float4*)&pp[4];
        float4 p2 = *(const float4*)&pp[8];
        float4 p3 = *(const float4*)&pp[12];
        float pv[16] = {p0.x, p0.y, p0.z, p0.w, p1.x, p1.y, p1.z, p1.w,
                        p2.x, p2.y, p2.z, p2.w, p3.x, p3.y, p3.z, p3.w};
        #pragma unroll
        for (int c = 0; c < 16; ++c)
            PHs[m * XS_STRIDE + c0 + c] = tanhf(acc[j][c] + pv[c]);
    }
    load_slab0(Ws, W2, tid);
    #pragma unroll
    for (int j = 0; j < 4; ++j)
        #pragma unroll
        for (int c = 0; c < 16; ++c) acc[j][c] = 0.f;
    __syncthreads();

    // ---- GEMM B: PH @ W2 ----
    gemm_tile(PHs, W2, Ws, acc, tid, r0, c0);

    // ---- epilogue B: + b2 + mg[seg], sigmoid, dot qw, alpha ----
    float4 bv0 = *(const float4*)&b2[c0 + 0];
    float4 bv1 = *(const float4*)&b2[c0 + 4];
    float4 bv2 = *(const float4*)&b2[c0 + 8];
    float4 bv3 = *(const float4*)&b2[c0 + 12];
    float bb[16] = {bv0.x, bv0.y, bv0.z, bv0.w, bv1.x, bv1.y, bv1.z, bv1.w,
                    bv2.x, bv2.y, bv2.z, bv2.w, bv3.x, bv3.y, bv3.z, bv3.w};
    float4 q0 = *(const float4*)&qw[c0 + 0];
    float4 q1 = *(const float4*)&qw[c0 + 4];
    float4 q2 = *(const float4*)&qw[c0 + 8];
    float4 q3 = *(const float4*)&qw[c0 + 12];
    float qv[16] = {q0.x, q0.y, q0.z, q0.w, q1.x, q1.y, q1.z, q1.w,
                    q2.x, q2.y, q2.z, q2.w, q3.x, q3.y, q3.z, q3.w};

    float part[4];
    #pragma unroll
    for (int j = 0; j < 4; ++j) {
        int m = r0 + j;
        const float* mgp = &g_mg[seg_s[m] * H + c0];
        float4 m0 = *(const float4*)&mgp[0];
        float4 m1 = *(const float4*)&mgp[4];
        float4 m2 = *(const float4*)&mgp[8];
        float4 m3 = *(const float4*)&mgp[12];
        float mv[16] = {m0.x, m0.y, m0.z, m0.w, m1.x, m1.y, m1.z, m1.w,
                        m2.x, m2.y, m2.z, m2.w, m3.x, m3.y, m3.z, m3.w};
        float p = 0.f;
        #pragma unroll
        for (int c = 0; c < 16; ++c) {
            float z = acc[j][c] + bb[c] + mv[c];
            float g = 1.f / (1.f + __expf(-z) * 0.f + expf(-z));   // keep accurate expf
            p = fmaf(g, qv[c], p);
        }
        part[j] = p;
    }
    // reduce across the 16 tx lanes sharing each row
    #pragma unroll
    for (int j = 0; j < 4; ++j) {
        #pragma unroll
        for (int o = 8; o > 0; o >>= 1)
            part[j] += __shfl_down_sync(0xffffffffu, part[j], o, 16);
    }
    if (tx == 0) {
        float qbv = qb[0];
        #pragma unroll
        for (int j = 0; j < 4; ++j) {
            int t = t0 + r0 + j;
            if (t < T) g_alpha[t] = part[j] + qbv;
        }
    }
}

// ---------------------------------------------------------------
// K6: h_s[b] = sum_t alpha[t] * hidden[t]. grid=nb, block=H
// ---------------------------------------------------------------
__global__ void k_finish(const float* __restrict__ hidden,
                         float* __restrict__ out, int nb) {
    int b = blockIdx.x;
    if (b >= nb) return;
    int s = g_offs[b], e = g_offs[b + 1];
    int tid = threadIdx.x;
    float acc = 0.f;
    #pragma unroll 4
    for (int t = s; t < e; ++t)
        acc = fmaf(g_alpha[t], hidden[t * H + tid], acc);
    out[b * H + tid] = acc;
}

// ---------------------------------------------------------------
extern "C" void kernel_launch(void* const* d_in, const int* in_sizes, int n_in,
                              void* d_out, int out_size) {
    const float* hidden      = (const float*)d_in[0];
    const float* pos_table   = (const float*)d_in[1];
    const float* W_pos       = (const float*)d_in[2];
    const float* b_pos       = (const float*)d_in[3];
    const float* W1          = (const float*)d_in[4];
    const float* b1          = (const float*)d_in[5];
    const float* W2          = (const float*)d_in[6];
    const float* b2          = (const float*)d_in[7];
    const float* qw          = (const float*)d_in[8];
    const float* qb          = (const float*)d_in[9];
    const int*   seq_len     = (const int*)d_in[10];
    const int*   reverse_pos = (const int*)d_in[11];

    int T    = in_sizes[0] / H;
    int nb   = in_sizes[10];
    int npos = in_sizes[1] / H;

    size_t smem_mg   = (size_t)(TM * XS_STRIDE + 2 * KK * H) * sizeof(float);
    size_t smem_main = (size_t)(2 * TM * XS_STRIDE + 2 * KK * H) * sizeof(float)
                     + (size_t)(2 * TM) * sizeof(int);
    cudaFuncSetAttribute(k_mg,   cudaFuncAttributeMaxDynamicSharedMemorySize, (int)smem_mg);
    cudaFuncSetAttribute(k_main, cudaFuncAttributeMaxDynamicSharedMemorySize, (int)smem_main);

    k_scan<<<1, 1024>>>(seq_len, nb);
    k_mean_seg<<<nb, H>>>(hidden, nb);
    k_posproj<<<npos, H>>>(pos_table, W_pos, b_pos);
    k_mg<<<(nb + TM - 1) / TM, 256, smem_mg>>>(W1, b1, nb);
    k_main<<<(T + TM - 1) / TM, 256, smem_main>>>(hidden, W_pos, W2, b2, qw, qb,
                                                  reverse_pos, T);
    k_finish<<<nb, H>>>(hidden, (float*)d_out, nb);
}

// round 2
// speedup vs baseline: 6.3111x; 6.3111x over previous
#include <cuda_runtime.h>
#include <math.h>
#include <stdint.h>

#define H 256
#define NB_MAX 4096
#define MAXT (4096 * 99)
#define TM 128          // tokens per CTA in mma kernels
#define SX 260          // Xs smem row stride (floats) - conflict-free A loads
#define SW 264          // W slab smem row stride (floats) - conflict-free B loads
#define KS 32           // K-slab rows per double-buffer stage

// ---- scratch (static __device__: allowed; no runtime allocation) ----
__device__ int   g_offs[NB_MAX + 1];
__device__ int   g_seg[MAXT];
__device__ float g_mean[NB_MAX * H];
__device__ float g_mg[NB_MAX * H];
__device__ float g_posproj[201 * H];
__device__ float g_alpha[MAXT];

// ---------------- PTX helpers ----------------
__device__ __forceinline__ void cp16(float* dst_smem, const float* src) {
    uint32_t d = (uint32_t)__cvta_generic_to_shared(dst_smem);
    asm volatile("cp.async.cg.shared.global [%0], [%1], 16;\n" :: "r"(d), "l"(src));
}
__device__ __forceinline__ void cp_commit() { asm volatile("cp.async.commit_group;\n"); }
__device__ __forceinline__ void cp_wait0()  { asm volatile("cp.async.wait_group 0;\n"); }

__device__ __forceinline__ void mma_tf32(float (&d)[4], const uint32_t (&a)[4],
                                         const uint32_t (&b)[2]) {
    asm volatile(
        "mma.sync.aligned.m16n8k8.row.col.f32.tf32.tf32.f32 "
        "{%0,%1,%2,%3}, {%4,%5,%6,%7}, {%8,%9}, {%0,%1,%2,%3};\n"
        : "+f"(d[0]), "+f"(d[1]), "+f"(d[2]), "+f"(d[3])
        : "r"(a[0]), "r"(a[1]), "r"(a[2]), "r"(a[3]), "r"(b[0]), "r"(b[1]));
}
__device__ __forceinline__ float fast_tanh(float x) {
    float r; asm("tanh.approx.f32 %0, %1;" : "=f"(r) : "f"(x)); return r;
}
__device__ __forceinline__ uint32_t to_tf32(float x) {
    uint32_t r; asm("cvt.rna.tf32.f32 %0, %1;" : "=r"(r) : "f"(x)); return r;
}

// ---------------------------------------------------------------
// K1: exclusive prefix scan of seq_len -> g_offs  (1 block, 1024 thr)
// ---------------------------------------------------------------
__global__ void k_scan(const int* __restrict__ seq_len, int nb) {
    __shared__ int chunk[1024];
    int tid = threadIdx.x;
    int base = tid * 4;
    int v0 = (base + 0 < nb) ? seq_len[base + 0] : 0;
    int v1 = (base + 1 < nb) ? seq_len[base + 1] : 0;
    int v2 = (base + 2 < nb) ? seq_len[base + 2] : 0;
    int v3 = (base + 3 < nb) ? seq_len[base + 3] : 0;
    int p1 = v0, p2 = v0 + v1, p3 = p2 + v2, p4 = p3 + v3;
    chunk[tid] = p4;
    __syncthreads();
    for (int d = 1; d < 1024; d <<= 1) {
        int t = (tid >= d) ? chunk[tid - d] : 0;
        __syncthreads();
        chunk[tid] += t;
        __syncthreads();
    }
    int prev = (tid > 0) ? chunk[tid - 1] : 0;
    if (base + 0 <= nb) g_offs[base + 0] = prev;
    if (base + 1 <= nb) g_offs[base + 1] = prev + p1;
    if (base + 2 <= nb) g_offs[base + 2] = prev + p2;
    if (base + 3 <= nb) g_offs[base + 3] = prev + p3;
    if (base + 4 <= nb) g_offs[base + 4] = prev + p4;
}

// ---------------------------------------------------------------
// K2: per-session mean + segment-id fill. grid=nb, block=H(256)
// ---------------------------------------------------------------
__global__ void k_mean_seg(const float* __restrict__ hidden, int nb) {
    int b = blockIdx.x;
    if (b >= nb) return;
    int s = g_offs[b], e = g_offs[b + 1];
    int tid = threadIdx.x;
    float a0 = 0.f, a1 = 0.f, a2 = 0.f, a3 = 0.f;
    int t = s;
    for (; t + 3 < e; t += 4) {
        a0 += hidden[(t + 0) * H + tid];
        a1 += hidden[(t + 1) * H + tid];
        a2 += hidden[(t + 2) * H + tid];
        a3 += hidden[(t + 3) * H + tid];
    }
    for (; t < e; ++t) a0 += hidden[t * H + tid];
    g_mean[b * H + tid] = (a0 + a1 + a2 + a3) / (float)(e - s);
    for (int u = s + tid; u < e; u += blockDim.x) g_seg[u] = b;
}

// ---------------------------------------------------------------
// K3: pos_proj[p,:] = pos_table[p,:] @ W_pos[H:,:] + b_pos. grid=201
// ---------------------------------------------------------------
__global__ void k_posproj(const float* __restrict__ pos_table,
                          const float* __restrict__ W_pos,
                          const float* __restrict__ b_pos) {
    __shared__ float row[H];
    int p = blockIdx.x;
    int c = threadIdx.x;
    row[c] = pos_table[p * H + c];
    __syncthreads();
    float acc = b_pos[c];
    #pragma unroll 8
    for (int k = 0; k < H; ++k)
        acc = fmaf(row[k], W_pos[(H + k) * H + c], acc);
    g_posproj[p * H + c] = acc;
}

// ---------------------------------------------------------------
// shared mma machinery
// ---------------------------------------------------------------
extern __shared__ float smem_dyn[];

__device__ __forceinline__ void stage_slab(float* dst, const float* Wg, int ks, int tid) {
    #pragma unroll
    for (int i = 0; i < 4; ++i) {
        int idx = tid + i * 512;            // 0..2047 float4s (32 x 256)
        int r = idx >> 6, c4 = (idx & 63) << 2;
        cp16(dst + r * SW + c4, Wg + (ks + r) * H + c4);
    }
}

// full K=256 GEMM: [TM,256](Xs) @ [256,256](Wg) -> acc.
// Ws0 must already hold slab 0 and be synced. Leaves all threads synced.
__device__ __forceinline__ void gemm_256(const float* __restrict__ Xs,
                                         const float* __restrict__ Wg,
                                         float* Ws0, float* Ws1,
                                         float acc[2][8][4],
                                         int tid, int lane, int R0, int C0) {
    float* bufs[2] = {Ws0, Ws1};
    for (int s = 0; s < 8; ++s) {
        const uint32_t* wp = (const uint32_t*)bufs[s & 1];
        if (s < 7) { stage_slab(bufs[(s + 1) & 1], Wg, (s + 1) * KS, tid); cp_commit(); }
        #pragma unroll
        for (int kk = 0; kk < 4; ++kk) {
            int k = s * KS + kk * 8;
            uint32_t a[2][4];
            const uint32_t* xp = (const uint32_t*)Xs;
            #pragma unroll
            for (int mb = 0; mb < 2; ++mb) {
                int r = R0 + mb * 16 + (lane >> 2);
                a[mb][0] = xp[r * SX + k + (lane & 3)];
                a[mb][1] = xp[(r + 8) * SX + k + (lane & 3)];
                a[mb][2] = xp[r * SX + k + (lane & 3) + 4];
                a[mb][3] = xp[(r + 8) * SX + k + (lane & 3) + 4];
            }
            int krow = kk * 8 + (lane & 3);
            int cb = C0 + (lane >> 2);
            uint32_t b[8][2];
            #pragma unroll
            for (int nt = 0; nt < 8; ++nt) {
                b[nt][0] = wp[krow * SW + cb + nt * 8];
                b[nt][1] = wp[(krow + 4) * SW + cb + nt * 8];
            }
            #pragma unroll
            for (int mb = 0; mb < 2; ++mb)
                #pragma unroll
                for (int nt = 0; nt < 8; ++nt)
                    mma_tf32(acc[mb][nt], a[mb], b[nt]);
        }
        if (s < 7) cp_wait0();
        __syncthreads();
    }
}

// ---------------------------------------------------------------
// K4: mg = mean @ W1 + b1  via tensor cores. grid = ceil(nb/TM), 512 thr
// ---------------------------------------------------------------
__global__ __launch_bounds__(512, 1) void k_mg_mma(const float* __restrict__ W1,
                                                   const float* __restrict__ b1, int nb) {
    float* Xs  = smem_dyn;               // TM*SX
    float* Ws0 = Xs + TM * SX;           // KS*SW
    float* Ws1 = Ws0 + KS * SW;          // KS*SW
    int tid = threadIdx.x, lane = tid & 31, wid = tid >> 5;
    int R0 = (wid >> 2) * 32, C0 = (wid & 3) * 64;
    int rb = blockIdx.x * TM;

    #pragma unroll
    for (int i = 0; i < 16; ++i) {
        int idx = tid + i * 512;         // 0..8191 float4s (128 x 64)
        int r = idx >> 6, c4 = (idx & 63) << 2;
        int src_r = rb + r < nb ? rb + r : nb - 1;
        cp16(Xs + r * SX + c4, g_mean + src_r * H + c4);
    }
    stage_slab(Ws0, W1, 0, tid);
    cp_commit(); cp_wait0();
    __syncthreads();

    float acc[2][8][4];
    #pragma unroll
    for (int mb = 0; mb < 2; ++mb)
        #pragma unroll
        for (int nt = 0; nt < 8; ++nt)
            #pragma unroll
            for (int j = 0; j < 4; ++j) acc[mb][nt][j] = 0.f;

    gemm_256(Xs, W1, Ws0, Ws1, acc, tid, lane, R0, C0);

    #pragma unroll
    for (int nt = 0; nt < 8; ++nt) {
        int c = C0 + nt * 8 + (lane & 3) * 2;
        float2 bv = *(const float2*)&b1[c];
        #pragma unroll
        for (int mb = 0; mb < 2; ++mb) {
            int r1 = rb + R0 + mb * 16 + (lane >> 2);
            int r2 = r1 + 8;
            if (r1 < nb) {
                float2 o = make_float2(acc[mb][nt][0] + bv.x, acc[mb][nt][1] + bv.y);
                *(float2*)&g_mg[r1 * H + c] = o;
            }
            if (r2 < nb) {
                float2 o = make_float2(acc[mb][nt][2] + bv.x, acc[mb][nt][3] + bv.y);
                *(float2*)&g_mg[r2 * H + c] = o;
            }
        }
    }
}

// ---------------------------------------------------------------
// K5: fused main kernel via tensor cores.
//   ph = tanh(X @ Wp_top + pos_proj[rp])
//   g  = sigmoid(ph @ W2 + b2 + mg[seg]);  alpha = g . qw + qb
// ---------------------------------------------------------------
__global__ __launch_bounds__(512, 1) void k_main_mma(const float* __restrict__ hidden,
                                                     const float* __restrict__ W_pos,
                                                     const float* __restrict__ W2,
                                                     const float* __restrict__ b2,
                                                     const float* __restrict__ qw,
                                                     const float* __restrict__ qb,
                                                     const int* __restrict__ reverse_pos,
                                                     int T) {
    float* Xs    = smem_dyn;                   // TM*SX
    float* Ws0   = Xs + TM * SX;               // KS*SW
    float* Ws1   = Ws0 + KS * SW;              // KS*SW
    float* partm = Ws1 + KS * SW;              // TM*4
    int*   rp_s  = (int*)(partm + TM * 4);     // TM
    int*   seg_s = rp_s + TM;                  // TM

    int tid = threadIdx.x, lane = tid & 31, wid = tid >> 5;
    int R0 = (wid >> 2) * 32, C0 = (wid & 3) * 64;
    int t0 = blockIdx.x * TM;

    // stage X tile + Wp slab0
    #pragma unroll
    for (int i = 0; i < 16; ++i) {
        int idx = tid + i * 512;
        int r = idx >> 6, c4 = (idx & 63) << 2;
        int src_r = (t0 + r < T) ? t0 + r : T - 1;
        cp16(Xs + r * SX + c4, hidden + src_r * H + c4);
    }
    stage_slab(Ws0, W_pos, 0, tid);   // Wp_top = first H rows of W_pos
    cp_commit();
    if (tid < TM) {
        int t = t0 + tid;
        rp_s[tid]  = (t < T) ? reverse_pos[t] : 0;
        seg_s[tid] = (t < T) ? g_seg[t] : 0;
    }
    cp_wait0();
    __syncthreads();

    float acc[2][8][4];
    #pragma unroll
    for (int mb = 0; mb < 2; ++mb)
        #pragma unroll
        for (int nt = 0; nt < 8; ++nt)
            #pragma unroll
            for (int j = 0; j < 4; ++j) acc[mb][nt][j] = 0.f;

    // ---- GEMM A: X @ Wp_top ----  (ends fully synced)
    gemm_256(Xs, W_pos, Ws0, Ws1, acc, tid, lane, R0, C0);

    // ---- epilogue A: + pos_proj gather, tanh -> overwrite Xs with PH ----
    // also start staging W2 slab0
    stage_slab(Ws0, W2, 0, tid);
    cp_commit();
    {
        int rowA = R0 + (lane >> 2);
        #pragma unroll
        for (int mb = 0; mb < 2; ++mb) {
            int r1 = rowA + mb * 16, r2 = r1 + 8;
            const float* pp1 = g_posproj + rp_s[r1] * H;
            const float* pp2 = g_posproj + rp_s[r2] * H;
            #pragma unroll
            for (int nt = 0; nt < 8; ++nt) {
                int c = C0 + nt * 8 + (lane & 3) * 2;
                float2 p1 = *(const float2*)&pp1[c];
                float2 p2 = *(const float2*)&pp2[c];
                float h0 = fast_tanh(acc[mb][nt][0] + p1.x);
                float h1 = fast_tanh(acc[mb][nt][1] + p1.y);
                float h2 = fast_tanh(acc[mb][nt][2] + p2.x);
                float h3 = fast_tanh(acc[mb][nt][3] + p2.y);
                float2 o1 = make_float2(__uint_as_float(to_tf32(h0)),
                                        __uint_as_float(to_tf32(h1)));
                float2 o2 = make_float2(__uint_as_float(to_tf32(h2)),
                                        __uint_as_float(to_tf32(h3)));
                *(float2*)&Xs[r1 * SX + c] = o1;
                *(float2*)&Xs[r2 * SX + c] = o2;
            }
        }
    }
    #pragma unroll
    for (int mb = 0; mb < 2; ++mb)
        #pragma unroll
        for (int nt = 0; nt < 8; ++nt)
            #pragma unroll
            for (int j = 0; j < 4; ++j) acc[mb][nt][j] = 0.f;
    cp_wait0();
    __syncthreads();

    // ---- GEMM B: PH @ W2 ----
    gemm_256(Xs, W2, Ws0, Ws1, acc, tid, lane, R0, C0);

    // ---- epilogue B: + b2 + mg[seg], sigmoid, dot qw ----
    float ps[2][2] = {{0.f, 0.f}, {0.f, 0.f}};
    int rowA = R0 + (lane >> 2);
    int sg[2][2];
    #pragma unroll
    for (int mb = 0; mb < 2; ++mb) {
        sg[mb][0] = seg_s[rowA + mb * 16];
        sg[mb][1] = seg_s[rowA + mb * 16 + 8];
    }
    #pragma unroll
    for (int nt = 0; nt < 8; ++nt) {
        int c = C0 + nt * 8 + (lane & 3) * 2;
        float2 bv = *(const float2*)&b2[c];
        float2 qv = *(const float2*)&qw[c];
        #pragma unroll
        for (int mb = 0; mb < 2; ++mb) {
            float2 m1 = *(const float2*)&g_mg[sg[mb][0] * H + c];
            float2 m2 = *(const float2*)&g_mg[sg[mb][1] * H + c];
            float z0 = acc[mb][nt][0] + bv.x + m1.x;
            float z1 = acc[mb][nt][1] + bv.y + m1.y;
            float z2 = acc[mb][nt][2] + bv.x + m2.x;
            float z3 = acc[mb][nt][3] + bv.y + m2.y;
            float g0 = 1.f / (1.f + __expf(-z0));
            float g1 = 1.f / (1.f + __expf(-z1));
            float g2 = 1.f / (1.f + __expf(-z2));
            float g3 = 1.f / (1.f + __expf(-z3));
            ps[mb][0] = fmaf(g0, qv.x, fmaf(g1, qv.y, ps[mb][0]));
            ps[mb][1] = fmaf(g2, qv.x, fmaf(g3, qv.y, ps[mb][1]));
        }
    }
    // reduce across the 4 lanes of each lane-group (they share the row)
    #pragma unroll
    for (int mb = 0; mb < 2; ++mb)
        #pragma unroll
        for (int hf = 0; hf < 2; ++hf) {
            ps[mb][hf] += __shfl_down_sync(0xffffffffu, ps[mb][hf], 2, 4);
            ps[mb][hf] += __shfl_down_sync(0xffffffffu, ps[mb][hf], 1, 4);
        }
    int cg = wid & 3;
    if ((lane & 3) == 0) {
        #pragma unroll
        for (int mb = 0; mb < 2; ++mb) {
            partm[(rowA + mb * 16) * 4 + cg]     = ps[mb][0];
            partm[(rowA + mb * 16 + 8) * 4 + cg] = ps[mb][1];
        }
    }
    __syncthreads();
    if (tid < TM) {
        int t = t0 + tid;
        if (t < T) {
            float a = partm[tid * 4 + 0] + partm[tid * 4 + 1] +
                      partm[tid * 4 + 2] + partm[tid * 4 + 3];
            g_alpha[t] = a + qb[0];
        }
    }
}

// ---------------------------------------------------------------
// K6: h_s[b] = sum_t alpha[t] * hidden[t]. grid=nb, block=H
// ---------------------------------------------------------------
__global__ void k_finish(const float* __restrict__ hidden,
                         float* __restrict__ out, int nb) {
    int b = blockIdx.x;
    if (b >= nb) return;
    int s = g_offs[b], e = g_offs[b + 1];
    int tid = threadIdx.x;
    float a0 = 0.f, a1 = 0.f, a2 = 0.f, a3 = 0.f;
    int t = s;
    for (; t + 3 < e; t += 4) {
        a0 = fmaf(g_alpha[t + 0], hidden[(t + 0) * H + tid], a0);
        a1 = fmaf(g_alpha[t + 1], hidden[(t + 1) * H + tid], a1);
        a2 = fmaf(g_alpha[t + 2], hidden[(t + 2) * H + tid], a2);
        a3 = fmaf(g_alpha[t + 3], hidden[(t + 3) * H + tid], a3);
    }
    for (; t < e; ++t) a0 = fmaf(g_alpha[t], hidden[t * H + tid], a0);
    out[b * H + tid] = (a0 + a1) + (a2 + a3);
}

// ---------------------------------------------------------------
extern "C" void kernel_launch(void* const* d_in, const int* in_sizes, int n_in,
                              void* d_out, int out_size) {
    const float* hidden      = (const float*)d_in[0];
    const float* pos_table   = (const float*)d_in[1];
    const float* W_pos       = (const float*)d_in[2];
    const float* b_pos       = (const float*)d_in[3];
    const float* W1          = (const float*)d_in[4];
    const float* b1          = (const float*)d_in[5];
    const float* W2          = (const float*)d_in[6];
    const float* b2          = (const float*)d_in[7];
    const float* qw          = (const float*)d_in[8];
    const float* qb          = (const float*)d_in[9];
    const int*   seq_len     = (const int*)d_in[10];
    const int*   reverse_pos = (const int*)d_in[11];

    int T    = in_sizes[0] / H;
    int nb   = in_sizes[10];
    int npos = in_sizes[1] / H;

    size_t smem_mg   = (size_t)(TM * SX + 2 * KS * SW) * sizeof(float);
    size_t smem_main = (size_t)(TM * SX + 2 * KS * SW + TM * 4) * sizeof(float)
                     + (size_t)(2 * TM) * sizeof(int);
    cudaFuncSetAttribute(k_mg_mma,   cudaFuncAttributeMaxDynamicSharedMemorySize, (int)smem_mg);
    cudaFuncSetAttribute(k_main_mma, cudaFuncAttributeMaxDynamicSharedMemorySize, (int)smem_main);

    k_scan<<<1, 1024>>>(seq_len, nb);
    k_mean_seg<<<nb, H>>>(hidden, nb);
    k_posproj<<<npos, H>>>(pos_table, W_pos, b_pos);
    k_mg_mma<<<(nb + TM - 1) / TM, 512, smem_mg>>>(W1, b1, nb);
    k_main_mma<<<(T + TM - 1) / TM, 512, smem_main>>>(hidden, W_pos, W2, b2, qw, qb,
                                                      reverse_pos, T);
    k_finish<<<nb, H>>>(hidden, (float*)d_out, nb);
}